// round 4
// baseline (speedup 1.0000x reference)
#include <cuda_runtime.h>

#define BB      512
#define INF     512
#define OUTF    64
#define KK      16
#define NN      1024   // OUTF * KK
#define OUTCOLS 576    // INF + OUTF

typedef unsigned long long ull;

// Scratch: M = x @ T.reshape(IN, OUT*K), shape (B, 1024), row-major.
__device__ float g_M[BB * NN];

#define FMA2D(d, a, b, c) \
    asm("fma.rn.f32x2 %0, %1, %2, %3;" : "=l"(d) : "l"(a), "l"(b), "l"(c))
#define ADD2(d, a, b) \
    asm("add.rn.f32x2 %0, %1, %2;" : "=l"(d) : "l"(a), "l"(b))

__device__ __forceinline__ void mma_tf32(float* c, const unsigned* a, const unsigned* b) {
    asm("mma.sync.aligned.m16n8k8.row.col.f32.tf32.tf32.f32 "
        "{%0,%1,%2,%3}, {%4,%5,%6,%7}, {%8,%9}, {%0,%1,%2,%3};"
        : "+f"(c[0]), "+f"(c[1]), "+f"(c[2]), "+f"(c[3])
        : "r"(a[0]), "r"(a[1]), "r"(a[2]), "r"(a[3]), "r"(b[0]), "r"(b[1]));
}

// ---------------------------------------------------------------------------
// GEMM via tf32 tensor cores (implicit truncation, no cvt):
// M = x(512x512) @ T(512x1024). Block: 128 threads, tile 32x64, k-tile 32.
// Grid (16,16) = 256 blocks. Warp (2x2) computes 16x32.
// Also initializes out[:, 512:576] to -1.0 (cancels the self exp(0) term).
// ---------------------------------------------------------------------------
__global__ __launch_bounds__(128) void gemm_tc(const float* __restrict__ x,
                                               const float* __restrict__ T,
                                               float* __restrict__ out) {
    __shared__ float As[32][36];   // [row][k], padded
    __shared__ float Bs[32][68];   // [k][n],  padded

    const int tid  = threadIdx.x;
    const int warp = tid >> 5;
    const int lane = tid & 31;
    const int wm   = warp & 1;     // warp row half (0..1)
    const int wn   = warp >> 1;    // warp col half (0..1)
    const int tg   = lane >> 2;    // 0..7
    const int tig  = lane & 3;     // 0..3

    const int rowBase = blockIdx.y * 32;
    const int colBase = blockIdx.x * 64;

    // Init the o_b region of out to -1.0 (exactly one element per thread).
    {
        int idx = (blockIdx.y * 16 + blockIdx.x) * 128 + tid;   // 0..32767
        out[(idx >> 6) * OUTCOLS + INF + (idx & 63)] = -1.0f;
    }

    float acc[4][4];
#pragma unroll
    for (int nt = 0; nt < 4; ++nt)
#pragma unroll
        for (int q = 0; q < 4; ++q) acc[nt][q] = 0.f;

    for (int k0 = 0; k0 < INF; k0 += 32) {
        // A tile: 32 rows x 32 k = 256 float4
#pragma unroll
        for (int t = tid; t < 256; t += 128) {
            int r  = t >> 3;
            int kq = (t & 7) * 4;
            *(float4*)&As[r][kq] = *(const float4*)&x[(rowBase + r) * INF + k0 + kq];
        }
        // B tile: 32 k x 64 n = 512 float4 (coalesced)
#pragma unroll
        for (int t = tid; t < 512; t += 128) {
            int kk = t >> 4;
            int nq = (t & 15) * 4;
            *(float4*)&Bs[kk][nq] = *(const float4*)&T[(k0 + kk) * NN + colBase + nq];
        }
        __syncthreads();

#pragma unroll
        for (int ks = 0; ks < 32; ks += 8) {
            unsigned a[4], b[4][2];
            int rowA = wm * 16 + tg;
            a[0] = __float_as_uint(As[rowA][ks + tig]);
            a[1] = __float_as_uint(As[rowA + 8][ks + tig]);
            a[2] = __float_as_uint(As[rowA][ks + tig + 4]);
            a[3] = __float_as_uint(As[rowA + 8][ks + tig + 4]);
#pragma unroll
            for (int nt = 0; nt < 4; ++nt) {
                int colB = wn * 32 + nt * 8 + tg;
                b[nt][0] = __float_as_uint(Bs[ks + tig][colB]);
                b[nt][1] = __float_as_uint(Bs[ks + tig + 4][colB]);
            }
#pragma unroll
            for (int nt = 0; nt < 4; ++nt)
                mma_tf32(acc[nt], a, b[nt]);
        }
        __syncthreads();
    }

#pragma unroll
    for (int nt = 0; nt < 4; ++nt) {
        int row0 = rowBase + wm * 16 + tg;
        int col0 = colBase + wn * 32 + nt * 8 + tig * 2;
        *(float2*)&g_M[row0 * NN + col0]       = make_float2(acc[nt][0], acc[nt][1]);
        *(float2*)&g_M[(row0 + 8) * NN + col0] = make_float2(acc[nt][2], acc[nt][3]);
    }
}

// ---------------------------------------------------------------------------
// Pairwise + folded x-copy. Grid (65, 8), 512 threads.
//   o < 64 : block (o, ec) handles j in [ec*64, ec*64+64) for ALL i (i = tid),
//            accumulating partial sums into out via atomicAdd.
//   o == 64: block ec copies x rows [ec*64, +64) into out[:, 0:512].
// ---------------------------------------------------------------------------
__global__ __launch_bounds__(512) void pairwise_kernel(const float* __restrict__ x,
                                                       float* __restrict__ out) {
    __shared__ __align__(16) float sK[64 * KK];   // 4 KB j-tile

    const int o   = blockIdx.x;
    const int ec  = blockIdx.y;
    const int tid = threadIdx.x;

    if (o == OUTF) {
        int base = ec * 64;
#pragma unroll
        for (int t = tid; t < 64 * (INF / 4); t += 512) {
            int r = t >> 7;
            int c = t & 127;
            float4 v = *(const float4*)&x[(base + r) * INF + c * 4];
            *(float4*)&out[(base + r) * OUTCOLS + c * 4] = v;
        }
        return;
    }

    const int jbase = ec * 64;

    // Load the 64-row j-tile for this o into smem (64 x 16 floats = 256 float4).
    if (tid < 256) {
        int r = tid >> 2;
        int q = tid & 3;
        *(float4*)&sK[r * KK + q * 4] =
            *(const float4*)&g_M[(jbase + r) * NN + o * KK + q * 4];
    }

    // Per-thread i-row from global (L2-resident).
    const int i = tid;
    ull mi[8];
    {
        const float4* mrow = (const float4*)&g_M[i * NN + o * KK];
        float4 a = mrow[0], b = mrow[1], c = mrow[2], d = mrow[3];
        mi[0] = ((ull)__float_as_uint(a.y) << 32) | __float_as_uint(a.x);
        mi[1] = ((ull)__float_as_uint(a.w) << 32) | __float_as_uint(a.z);
        mi[2] = ((ull)__float_as_uint(b.y) << 32) | __float_as_uint(b.x);
        mi[3] = ((ull)__float_as_uint(b.w) << 32) | __float_as_uint(b.z);
        mi[4] = ((ull)__float_as_uint(c.y) << 32) | __float_as_uint(c.x);
        mi[5] = ((ull)__float_as_uint(c.w) << 32) | __float_as_uint(c.z);
        mi[6] = ((ull)__float_as_uint(d.y) << 32) | __float_as_uint(d.x);
        mi[7] = ((ull)__float_as_uint(d.w) << 32) | __float_as_uint(d.z);
    }
    __syncthreads();

    const ull NEG1  = 0xBF800000BF800000ULL;   // (-1.f, -1.f)
    const ull AMASK = 0x7FFFFFFF7FFFFFFFULL;

    float acc = 0.f;
#pragma unroll 4
    for (int jj = 0; jj < 64; ++jj) {
        const ulonglong2* p = (const ulonglong2*)&sK[jj * KK];
        ulonglong2 p0 = p[0], p1 = p[1], p2 = p[2], p3 = p[3];

        ull d0, d1, d2, d3, d4, d5, d6, d7;
        FMA2D(d0, p0.x, NEG1, mi[0]);   // mi - mj, 2 lanes per op
        FMA2D(d1, p0.y, NEG1, mi[1]);
        FMA2D(d2, p1.x, NEG1, mi[2]);
        FMA2D(d3, p1.y, NEG1, mi[3]);
        FMA2D(d4, p2.x, NEG1, mi[4]);
        FMA2D(d5, p2.y, NEG1, mi[5]);
        FMA2D(d6, p3.x, NEG1, mi[6]);
        FMA2D(d7, p3.y, NEG1, mi[7]);

        d0 &= AMASK; d1 &= AMASK; d2 &= AMASK; d3 &= AMASK;   // |.| on ALU pipe
        d4 &= AMASK; d5 &= AMASK; d6 &= AMASK; d7 &= AMASK;

        ull s0, s1, s2, s3, t0, t1, tt;
        ADD2(s0, d0, d1);
        ADD2(s1, d2, d3);
        ADD2(s2, d4, d5);
        ADD2(s3, d6, d7);
        ADD2(t0, s0, s1);
        ADD2(t1, s2, s3);
        ADD2(tt, t0, t1);

        float lo = __uint_as_float((unsigned int)tt);
        float hi = __uint_as_float((unsigned int)(tt >> 32));
        float norm = lo + hi;

        acc += __expf(-norm);          // j==i contributes exactly 1.0 (cancelled by -1 init)
    }

    atomicAdd(&out[i * OUTCOLS + INF + o], acc);
}

extern "C" void kernel_launch(void* const* d_in, const int* in_sizes, int n_in,
                              void* d_out, int out_size) {
    const float* x = (const float*)d_in[0];
    const float* T = (const float*)d_in[1];
    float* out = (float*)d_out;

    gemm_tc<<<dim3(NN / 64, BB / 32), 128>>>(x, T, out);
    pairwise_kernel<<<dim3(OUTF + 1, 8), 512>>>(x, out);
}

// round 5
// speedup vs baseline: 1.2643x; 1.2643x over previous
#include <cuda_runtime.h>

#define BB      512
#define INF     512
#define OUTF    64
#define KK      16
#define NN      1024   // OUTF * KK
#define OUTCOLS 576    // INF + OUTF
#define THRESH  120.0f

typedef unsigned long long ull;

// Scratch (static device allocs are allowed).
__device__ float g_M[BB * NN];              // 2MB: M = x @ T
__device__ float g_G[OUTF * BB * 8];        // 1MB: 8 group-sums per (o,i)
__device__ ull   g_mask[OUTF * 8 * BB];     // 2MB: survivor bitmasks

#define FMA2D(d, a, b, c) \
    asm("fma.rn.f32x2 %0, %1, %2, %3;" : "=l"(d) : "l"(a), "l"(b), "l"(c))
#define ADD2(d, a, b) \
    asm("add.rn.f32x2 %0, %1, %2;" : "=l"(d) : "l"(a), "l"(b))

__device__ __forceinline__ void mma_tf32(float* c, const unsigned* a, const unsigned* b) {
    asm("mma.sync.aligned.m16n8k8.row.col.f32.tf32.tf32.f32 "
        "{%0,%1,%2,%3}, {%4,%5,%6,%7}, {%8,%9}, {%0,%1,%2,%3};"
        : "+f"(c[0]), "+f"(c[1]), "+f"(c[2]), "+f"(c[3])
        : "r"(a[0]), "r"(a[1]), "r"(a[2]), "r"(a[3]), "r"(b[0]), "r"(b[1]));
}

// ---------------------------------------------------------------------------
// GEMM via tf32 tensor cores: M = x(512x512) @ T(512x1024).
// Block 128 thr, tile 32x64, k-tile 32, grid (16,16)=256.
// ---------------------------------------------------------------------------
__global__ __launch_bounds__(128) void gemm_tc(const float* __restrict__ x,
                                               const float* __restrict__ T) {
    __shared__ float As[32][36];
    __shared__ float Bs[32][68];

    const int tid  = threadIdx.x;
    const int warp = tid >> 5;
    const int lane = tid & 31;
    const int wm   = warp & 1;
    const int wn   = warp >> 1;
    const int tg   = lane >> 2;
    const int tig  = lane & 3;

    const int rowBase = blockIdx.y * 32;
    const int colBase = blockIdx.x * 64;

    float acc[4][4];
#pragma unroll
    for (int nt = 0; nt < 4; ++nt)
#pragma unroll
        for (int q = 0; q < 4; ++q) acc[nt][q] = 0.f;

    for (int k0 = 0; k0 < INF; k0 += 32) {
#pragma unroll
        for (int t = tid; t < 256; t += 128) {
            int r  = t >> 3;
            int kq = (t & 7) * 4;
            *(float4*)&As[r][kq] = *(const float4*)&x[(rowBase + r) * INF + k0 + kq];
        }
#pragma unroll
        for (int t = tid; t < 512; t += 128) {
            int kk = t >> 4;
            int nq = (t & 15) * 4;
            *(float4*)&Bs[kk][nq] = *(const float4*)&T[(k0 + kk) * NN + colBase + nq];
        }
        __syncthreads();

#pragma unroll
        for (int ks = 0; ks < 32; ks += 8) {
            unsigned a[4], b[4][2];
            int rowA = wm * 16 + tg;
            a[0] = __float_as_uint(As[rowA][ks + tig]);
            a[1] = __float_as_uint(As[rowA + 8][ks + tig]);
            a[2] = __float_as_uint(As[rowA][ks + tig + 4]);
            a[3] = __float_as_uint(As[rowA + 8][ks + tig + 4]);
#pragma unroll
            for (int nt = 0; nt < 4; ++nt) {
                int colB = wn * 32 + nt * 8 + tg;
                b[nt][0] = __float_as_uint(Bs[ks + tig][colB]);
                b[nt][1] = __float_as_uint(Bs[ks + tig + 4][colB]);
            }
#pragma unroll
            for (int nt = 0; nt < 4; ++nt)
                mma_tf32(acc[nt], a, b[nt]);
        }
        __syncthreads();
    }

#pragma unroll
    for (int nt = 0; nt < 4; ++nt) {
        int row0 = rowBase + wm * 16 + tg;
        int col0 = colBase + wn * 32 + nt * 8 + tig * 2;
        *(float2*)&g_M[row0 * NN + col0]       = make_float2(acc[nt][0], acc[nt][1]);
        *(float2*)&g_M[(row0 + 8) * NN + col0] = make_float2(acc[nt][2], acc[nt][3]);
    }
}

// ---------------------------------------------------------------------------
// Per (i,o): 8 group sums (pairs of adjacent k), stored G[o][i][g].
// Also zero-inits the o_b block of out. Grid 128 x 256 threads.
// ---------------------------------------------------------------------------
__global__ __launch_bounds__(256) void gsum_zero(float* __restrict__ out) {
    int idx = blockIdx.x * 256 + threadIdx.x;   // 0..32767
    int i = idx >> 6;
    int o = idx & 63;

    const float4* row = (const float4*)&g_M[i * NN + o * KK];
    float4 a = row[0], b = row[1], c = row[2], d = row[3];

    float g[8];
    g[0] = a.x + a.y;  g[1] = a.z + a.w;
    g[2] = b.x + b.y;  g[3] = b.z + b.w;
    g[4] = c.x + c.y;  g[5] = c.z + c.w;
    g[6] = d.x + d.y;  g[7] = d.z + d.w;

    float* dst = &g_G[((o << 9) + i) * 8];
    *(float4*)&dst[0] = make_float4(g[0], g[1], g[2], g[3]);
    *(float4*)&dst[4] = make_float4(g[4], g[5], g[6], g[7]);

    out[i * OUTCOLS + INF + o] = 0.f;
}

// ---------------------------------------------------------------------------
// Stage 1: lower-bound filter -> bitmask.  Grid (65, 8), 512 threads.
//   o < 64 : block (o, ec): i = tid, j in [ec*64, ec*64+64).
//            lb = sum_g |G_i,g - G_j,g| ; bit set if lb < THRESH.
//   o == 64: copy x rows into out[:, 0:512].
// ---------------------------------------------------------------------------
__global__ __launch_bounds__(512) void stage1_mask(const float* __restrict__ x,
                                                   float* __restrict__ out) {
    __shared__ __align__(16) ull sG[64 * 4];   // 64 j-rows x 4 packed group-pairs

    const int o   = blockIdx.x;
    const int ec  = blockIdx.y;
    const int tid = threadIdx.x;

    if (o == OUTF) {
        int base = ec * 64;
#pragma unroll
        for (int t = tid; t < 64 * (INF / 4); t += 512) {
            int r = t >> 7;
            int c = t & 127;
            float4 v = *(const float4*)&x[(base + r) * INF + c * 4];
            *(float4*)&out[(base + r) * OUTCOLS + c * 4] = v;
        }
        return;
    }

    const int jbase = ec * 64;

    // Load G tile for j-rows: 64 rows x 32B = 128 float4 loads.
    if (tid < 128) {
        int r = tid >> 1;          // 0..63
        int h = tid & 1;           // half
        *(float4*)&sG[r * 4 + h * 2] =
            *(const float4*)&g_G[((o << 9) + jbase + r) * 8 + h * 4];
    }

    const int i = tid;
    ull gi[4];
    {
        const ulonglong2* p = (const ulonglong2*)&g_G[((o << 9) + i) * 8];
        ulonglong2 v0 = p[0], v1 = p[1];
        gi[0] = v0.x; gi[1] = v0.y; gi[2] = v1.x; gi[3] = v1.y;
    }
    __syncthreads();

    const ull NEG1  = 0xBF800000BF800000ULL;
    const ull AMASK = 0x7FFFFFFF7FFFFFFFULL;

    ull msk = 0;
#pragma unroll
    for (int jj = 0; jj < 64; ++jj) {
        const ulonglong2* p = (const ulonglong2*)&sG[jj * 4];
        ulonglong2 v0 = p[0], v1 = p[1];

        ull d0, d1, d2, d3;
        FMA2D(d0, v0.x, NEG1, gi[0]);
        FMA2D(d1, v0.y, NEG1, gi[1]);
        FMA2D(d2, v1.x, NEG1, gi[2]);
        FMA2D(d3, v1.y, NEG1, gi[3]);
        d0 &= AMASK; d1 &= AMASK; d2 &= AMASK; d3 &= AMASK;

        ull s0, s1, t;
        ADD2(s0, d0, d1);
        ADD2(s1, d2, d3);
        ADD2(t, s0, s1);

        float lb = __uint_as_float((unsigned)t) + __uint_as_float((unsigned)(t >> 32));
        if (lb < THRESH) msk |= (1ULL << jj);
    }

    g_mask[(o * 8 + ec) * 512 + i] = msk;
}

// ---------------------------------------------------------------------------
// Stage 2: scan bitmask, compute exact exp(-L1) for survivors, atomicAdd.
// Grid 256 x 256, grid-stride over 262144 mask words.
// ---------------------------------------------------------------------------
__global__ __launch_bounds__(256) void stage2_exact(float* __restrict__ out) {
    const int NW = OUTF * 8 * BB;   // 262144
    for (int widx = blockIdx.x * 256 + threadIdx.x; widx < NW; widx += 256 * 256) {
        ull w = g_mask[widx];
        if (!w) continue;
        int o  = widx >> 12;
        int ec = (widx >> 9) & 7;
        int i  = widx & 511;

        const float4* ri = (const float4*)&g_M[i * NN + o * KK];
        float4 a = ri[0], b = ri[1], c = ri[2], d = ri[3];

        float acc = 0.f;
        while (w) {
            int bit = __ffsll((long long)w) - 1;
            w &= w - 1;
            int j = ec * 64 + bit;
            if (j == i) continue;

            const float4* rj = (const float4*)&g_M[j * NN + o * KK];
            float4 e = rj[0], f = rj[1], g = rj[2], h = rj[3];

            float norm =
                fabsf(a.x - e.x) + fabsf(a.y - e.y) + fabsf(a.z - e.z) + fabsf(a.w - e.w) +
                fabsf(b.x - f.x) + fabsf(b.y - f.y) + fabsf(b.z - f.z) + fabsf(b.w - f.w) +
                fabsf(c.x - g.x) + fabsf(c.y - g.y) + fabsf(c.z - g.z) + fabsf(c.w - g.w) +
                fabsf(d.x - h.x) + fabsf(d.y - h.y) + fabsf(d.z - h.z) + fabsf(d.w - h.w);

            acc += __expf(-norm);
        }
        if (acc != 0.f)
            atomicAdd(&out[i * OUTCOLS + INF + o], acc);
    }
}

extern "C" void kernel_launch(void* const* d_in, const int* in_sizes, int n_in,
                              void* d_out, int out_size) {
    const float* x = (const float*)d_in[0];
    const float* T = (const float*)d_in[1];
    float* out = (float*)d_out;

    gemm_tc<<<dim3(NN / 64, BB / 32), 128>>>(x, T);
    gsum_zero<<<128, 256>>>(out);
    stage1_mask<<<dim3(OUTF + 1, 8), 512>>>(x, out);
    stage2_exact<<<256, 256>>>(out);
}

// round 6
// speedup vs baseline: 1.6980x; 1.3431x over previous
#include <cuda_runtime.h>

#define BB      512
#define INF     512
#define OUTF    64
#define KK      16
#define NN      1024   // OUTF * KK
#define OUTCOLS 576    // INF + OUTF
#define THRESH  120.0f

typedef unsigned long long ull;

// Scratch (static device allocs are allowed).
__device__ float g_M[BB * NN];              // 2MB: M = x @ T
__device__ float g_G[OUTF * BB * 8];        // 1MB: 8 group-sums per (o,i)
__device__ ull   g_mask[OUTF * 8 * BB];     // 2MB: survivor bitmasks (j>i only)

#define FMA2D(d, a, b, c) \
    asm("fma.rn.f32x2 %0, %1, %2, %3;" : "=l"(d) : "l"(a), "l"(b), "l"(c))
#define ADD2(d, a, b) \
    asm("add.rn.f32x2 %0, %1, %2;" : "=l"(d) : "l"(a), "l"(b))

__device__ __forceinline__ void mma_tf32(float* c, const unsigned* a, const unsigned* b) {
    asm("mma.sync.aligned.m16n8k8.row.col.f32.tf32.tf32.f32 "
        "{%0,%1,%2,%3}, {%4,%5,%6,%7}, {%8,%9}, {%0,%1,%2,%3};"
        : "+f"(c[0]), "+f"(c[1]), "+f"(c[2]), "+f"(c[3])
        : "r"(a[0]), "r"(a[1]), "r"(a[2]), "r"(a[3]), "r"(b[0]), "r"(b[1]));
}

// ---------------------------------------------------------------------------
// GEMM via tf32 tensor cores, double-buffered: M = x(512x512) @ T(512x1024).
// Block 128 thr, tile 32x64, k-tile 32, grid (16,16)=256.
// Epilogue writes g_M + group sums g_G, and zero-inits out[:,512:576].
// ---------------------------------------------------------------------------
__global__ __launch_bounds__(128) void gemm_tc(const float* __restrict__ x,
                                               const float* __restrict__ T,
                                               float* __restrict__ out) {
    __shared__ float As[2][32][36];
    __shared__ float Bs[2][32][68];

    const int tid  = threadIdx.x;
    const int warp = tid >> 5;
    const int lane = tid & 31;
    const int wm   = warp & 1;
    const int wn   = warp >> 1;
    const int tg   = lane >> 2;
    const int tig  = lane & 3;

    const int rowBase = blockIdx.y * 32;
    const int colBase = blockIdx.x * 64;

    // Zero-init the o_b region (one element per thread across the grid).
    {
        int idx = (blockIdx.y * 16 + blockIdx.x) * 128 + tid;   // 0..32767
        out[(idx >> 6) * OUTCOLS + INF + (idx & 63)] = 0.f;
    }

    const int ar  = tid >> 3;            // A row this thread loads (0..15, +16)
    const int akq = (tid & 7) * 4;       // A k-quad
    const int bk  = tid >> 4;            // B k row (0..7, +8,+16,+24)
    const int bnq = (tid & 15) * 4;      // B n-quad

    // Prologue: tile 0 -> buffer 0.
    *(float4*)&As[0][ar][akq]      = *(const float4*)&x[(rowBase + ar) * INF + akq];
    *(float4*)&As[0][ar + 16][akq] = *(const float4*)&x[(rowBase + ar + 16) * INF + akq];
#pragma unroll
    for (int m = 0; m < 4; ++m)
        *(float4*)&Bs[0][bk + m * 8][bnq] =
            *(const float4*)&T[(bk + m * 8) * NN + colBase + bnq];
    __syncthreads();

    float acc[4][4];
#pragma unroll
    for (int nt = 0; nt < 4; ++nt)
#pragma unroll
        for (int q = 0; q < 4; ++q) acc[nt][q] = 0.f;

    float4 pa0, pa1, pb[4];

    for (int it = 0; it < 16; ++it) {
        const int cur = it & 1;
        const int nxt = cur ^ 1;
        const int k0n = (it + 1) * 32;

        if (it < 15) {   // prefetch next tile into registers
            pa0 = *(const float4*)&x[(rowBase + ar) * INF + k0n + akq];
            pa1 = *(const float4*)&x[(rowBase + ar + 16) * INF + k0n + akq];
#pragma unroll
            for (int m = 0; m < 4; ++m)
                pb[m] = *(const float4*)&T[(k0n + bk + m * 8) * NN + colBase + bnq];
        }

#pragma unroll
        for (int ks = 0; ks < 32; ks += 8) {
            unsigned a[4], b[4][2];
            int rowA = wm * 16 + tg;
            a[0] = __float_as_uint(As[cur][rowA][ks + tig]);
            a[1] = __float_as_uint(As[cur][rowA + 8][ks + tig]);
            a[2] = __float_as_uint(As[cur][rowA][ks + tig + 4]);
            a[3] = __float_as_uint(As[cur][rowA + 8][ks + tig + 4]);
#pragma unroll
            for (int nt = 0; nt < 4; ++nt) {
                int colB = wn * 32 + nt * 8 + tg;
                b[nt][0] = __float_as_uint(Bs[cur][ks + tig][colB]);
                b[nt][1] = __float_as_uint(Bs[cur][ks + tig + 4][colB]);
            }
#pragma unroll
            for (int nt = 0; nt < 4; ++nt)
                mma_tf32(acc[nt], a, b[nt]);
        }

        if (it < 15) {
            *(float4*)&As[nxt][ar][akq]      = pa0;
            *(float4*)&As[nxt][ar + 16][akq] = pa1;
#pragma unroll
            for (int m = 0; m < 4; ++m)
                *(float4*)&Bs[nxt][bk + m * 8][bnq] = pb[m];
            __syncthreads();
        }
    }

    // Epilogue: g_M and group sums g_G (adjacent col pairs = adjacent k pairs).
#pragma unroll
    for (int nt = 0; nt < 4; ++nt) {
        int row0 = rowBase + wm * 16 + tg;
        int col0 = colBase + wn * 32 + nt * 8 + tig * 2;
        int o = col0 >> 4;
        int g = (col0 & 15) >> 1;
        *(float2*)&g_M[row0 * NN + col0]       = make_float2(acc[nt][0], acc[nt][1]);
        *(float2*)&g_M[(row0 + 8) * NN + col0] = make_float2(acc[nt][2], acc[nt][3]);
        g_G[((o << 9) + row0) * 8 + g]     = acc[nt][0] + acc[nt][1];
        g_G[((o << 9) + row0 + 8) * 8 + g] = acc[nt][2] + acc[nt][3];
    }
}

// ---------------------------------------------------------------------------
// Stage 1: symmetric lower-bound filter -> bitmask (bits only for j > i).
// Grid (65, 8), 512 threads. o == 64: copy x rows into out[:, 0:512].
// ---------------------------------------------------------------------------
__global__ __launch_bounds__(512) void stage1_mask(const float* __restrict__ x,
                                                   float* __restrict__ out) {
    __shared__ __align__(16) ull sG[64 * 4];   // 64 j-rows x 4 packed group-pairs

    const int o   = blockIdx.x;
    const int ec  = blockIdx.y;
    const int tid = threadIdx.x;

    if (o == OUTF) {
        int base = ec * 64;
#pragma unroll
        for (int t = tid; t < 64 * (INF / 4); t += 512) {
            int r = t >> 7;
            int c = t & 127;
            float4 v = *(const float4*)&x[(base + r) * INF + c * 4];
            *(float4*)&out[(base + r) * OUTCOLS + c * 4] = v;
        }
        return;
    }

    const int jbase = ec * 64;
    const int i     = tid;
    const int lim   = i - jbase;   // bits jj <= lim must be cleared (j > i only)

    if (tid < 128) {
        int r = tid >> 1;
        int h = tid & 1;
        *(float4*)&sG[r * 4 + h * 2] =
            *(const float4*)&g_G[((o << 9) + jbase + r) * 8 + h * 4];
    }

    ull gi[4];
    {
        const ulonglong2* p = (const ulonglong2*)&g_G[((o << 9) + i) * 8];
        ulonglong2 v0 = p[0], v1 = p[1];
        gi[0] = v0.x; gi[1] = v0.y; gi[2] = v1.x; gi[3] = v1.y;
    }
    __syncthreads();

    const ull NEG1  = 0xBF800000BF800000ULL;
    const ull AMASK = 0x7FFFFFFF7FFFFFFFULL;

    ull msk = 0;
    if (lim < 63) {
#pragma unroll
        for (int jj = 0; jj < 64; ++jj) {
            const ulonglong2* p = (const ulonglong2*)&sG[jj * 4];
            ulonglong2 v0 = p[0], v1 = p[1];

            ull d0, d1, d2, d3;
            FMA2D(d0, v0.x, NEG1, gi[0]);
            FMA2D(d1, v0.y, NEG1, gi[1]);
            FMA2D(d2, v1.x, NEG1, gi[2]);
            FMA2D(d3, v1.y, NEG1, gi[3]);
            d0 &= AMASK; d1 &= AMASK; d2 &= AMASK; d3 &= AMASK;

            ull s0, s1, t;
            ADD2(s0, d0, d1);
            ADD2(s1, d2, d3);
            ADD2(t, s0, s1);

            float lb = __uint_as_float((unsigned)t) + __uint_as_float((unsigned)(t >> 32));
            if (lb < THRESH) msk |= (1ULL << jj);
        }
        if (lim >= 0) msk &= ~((2ULL << lim) - 1ULL);
    }

    g_mask[(o * 8 + ec) * 512 + i] = msk;
}

// ---------------------------------------------------------------------------
// Stage 2: one thread per mask word; exact exp(-L1) for survivors,
// added to BOTH out[i,o] and out[j,o] (j > i). Grid 1024 x 256.
// ---------------------------------------------------------------------------
__global__ __launch_bounds__(256) void stage2_exact(float* __restrict__ out) {
    const int widx = blockIdx.x * 256 + threadIdx.x;   // 0..262143
    ull w = g_mask[widx];
    if (!w) return;

    const int o  = widx >> 12;
    const int ec = (widx >> 9) & 7;
    const int i  = widx & 511;

    const float4* ri = (const float4*)&g_M[i * NN + o * KK];
    float4 a = ri[0], b = ri[1], c = ri[2], d = ri[3];

    float acc = 0.f;
    while (w) {
        int bit = __ffsll((long long)w) - 1;
        w &= w - 1;
        int j = ec * 64 + bit;

        const float4* rj = (const float4*)&g_M[j * NN + o * KK];
        float4 e = rj[0], f = rj[1], g = rj[2], h = rj[3];

        float norm =
            fabsf(a.x - e.x) + fabsf(a.y - e.y) + fabsf(a.z - e.z) + fabsf(a.w - e.w) +
            fabsf(b.x - f.x) + fabsf(b.y - f.y) + fabsf(b.z - f.z) + fabsf(b.w - f.w) +
            fabsf(c.x - g.x) + fabsf(c.y - g.y) + fabsf(c.z - g.z) + fabsf(c.w - g.w) +
            fabsf(d.x - h.x) + fabsf(d.y - h.y) + fabsf(d.z - h.z) + fabsf(d.w - h.w);

        float ev = __expf(-norm);
        acc += ev;
        if (ev != 0.f)
            atomicAdd(&out[j * OUTCOLS + INF + o], ev);
    }
    if (acc != 0.f)
        atomicAdd(&out[i * OUTCOLS + INF + o], acc);
}

extern "C" void kernel_launch(void* const* d_in, const int* in_sizes, int n_in,
                              void* d_out, int out_size) {
    const float* x = (const float*)d_in[0];
    const float* T = (const float*)d_in[1];
    float* out = (float*)d_out;

    gemm_tc<<<dim3(NN / 64, BB / 32), 128>>>(x, T, out);
    stage1_mask<<<dim3(OUTF + 1, 8), 512>>>(x, out);
    stage2_exact<<<1024, 256>>>(out);
}